// round 5
// baseline (speedup 1.0000x reference)
#include <cuda_runtime.h>
#include <cuda_bf16.h>

#define B_    8
#define T_    400
#define U_    60
#define U1_   61
#define E_    256
#define H_    512
#define V_    28
#define BLANK_ 27
#define HC_   64
#define NEGF  (-1e30f)
#define LOG2E 1.4426950408889634f
#define LN2   0.6931471805599453f

// Scratch (no cudaMalloc allowed)
__device__ float g_F[B_*T_*H_];        // enc@We + bf   (3200 x 512)
__device__ float g_G[B_*U1_*H_];       // dec@Wd        (488 x 512)
__device__ float g_blank[B_*T_*U1_];   // blank log-probs
__device__ float g_lab[B_*T_*U1_];     // label log-probs (u < 60 valid)

__device__ __forceinline__ float fast_tanh(float x) {
    float y;
    asm("tanh.approx.f32 %0, %1;" : "=f"(y) : "f"(x));
    return y;
}
__device__ __forceinline__ float fast_ex2(float x) {
    float y;
    asm("ex2.approx.f32 %0, %1;" : "=f"(y) : "f"(x));
    return y;
}
__device__ __forceinline__ float fast_lg2(float x) {
    float y;
    asm("lg2.approx.f32 %0, %1;" : "=f"(y) : "f"(x));
    return y;
}

// ---------------------------------------------------------------------------
// Tiled fp32 GEMM: C[M,N] = A[M,K] @ B[K,N] (+ bias[N]).  64x64 tile, 4x4 micro.
// ---------------------------------------------------------------------------
__global__ void gemm_bias_kernel(const float* __restrict__ A,
                                 const float* __restrict__ Bm,
                                 const float* __restrict__ bias,
                                 float* __restrict__ C,
                                 int M, int N, int K)
{
    __shared__ float As[16][65];
    __shared__ float Bs[16][64];
    int tid = threadIdx.x;               // 256 threads
    int tx = tid & 15, ty = tid >> 4;
    int mb = blockIdx.y * 64, nb = blockIdx.x * 64;

    float acc[4][4];
    #pragma unroll
    for (int i = 0; i < 4; i++)
        #pragma unroll
        for (int j = 0; j < 4; j++) acc[i][j] = 0.f;

    for (int k0 = 0; k0 < K; k0 += 16) {
        {
            int r = tid >> 2;
            int q = (tid & 3) << 2;
            float4 av = make_float4(0.f, 0.f, 0.f, 0.f);
            int gm = mb + r;
            if (gm < M) av = *(const float4*)(A + (size_t)gm * K + k0 + q);
            As[q + 0][r] = av.x; As[q + 1][r] = av.y;
            As[q + 2][r] = av.z; As[q + 3][r] = av.w;
        }
        {
            int rk = tid >> 4;
            int qc = (tid & 15) << 2;
            float4 bv = *(const float4*)(Bm + (size_t)(k0 + rk) * N + nb + qc);
            *(float4*)&Bs[rk][qc] = bv;
        }
        __syncthreads();

        #pragma unroll
        for (int kk = 0; kk < 16; kk++) {
            float a0 = As[kk][ty * 4 + 0];
            float a1 = As[kk][ty * 4 + 1];
            float a2 = As[kk][ty * 4 + 2];
            float a3 = As[kk][ty * 4 + 3];
            float4 b4 = *(float4*)&Bs[kk][tx * 4];
            acc[0][0] = fmaf(a0, b4.x, acc[0][0]);
            acc[0][1] = fmaf(a0, b4.y, acc[0][1]);
            acc[0][2] = fmaf(a0, b4.z, acc[0][2]);
            acc[0][3] = fmaf(a0, b4.w, acc[0][3]);
            acc[1][0] = fmaf(a1, b4.x, acc[1][0]);
            acc[1][1] = fmaf(a1, b4.y, acc[1][1]);
            acc[1][2] = fmaf(a1, b4.z, acc[1][2]);
            acc[1][3] = fmaf(a1, b4.w, acc[1][3]);
            acc[2][0] = fmaf(a2, b4.x, acc[2][0]);
            acc[2][1] = fmaf(a2, b4.y, acc[2][1]);
            acc[2][2] = fmaf(a2, b4.z, acc[2][2]);
            acc[2][3] = fmaf(a2, b4.w, acc[2][3]);
            acc[3][0] = fmaf(a3, b4.x, acc[3][0]);
            acc[3][1] = fmaf(a3, b4.y, acc[3][1]);
            acc[3][2] = fmaf(a3, b4.z, acc[3][2]);
            acc[3][3] = fmaf(a3, b4.w, acc[3][3]);
        }
        __syncthreads();
    }

    #pragma unroll
    for (int i = 0; i < 4; i++) {
        int gm = mb + ty * 4 + i;
        if (gm < M) {
            #pragma unroll
            for (int j = 0; j < 4; j++) {
                int gn = nb + tx * 4 + j;
                float bb = bias ? bias[gn] : 0.f;
                C[(size_t)gm * N + gn] = acc[i][j] + bb;
            }
        }
    }
}

// ---------------------------------------------------------------------------
// Fused joint kernel, SCALAR fp32 FMAs (f32x2 regressed), 2 t-rows per thread.
// Block (64,4): u = threadIdx.x (0..60 active), tl = threadIdx.y (0..3).
// Thread computes t rows t0+tl and t0+tl+4; block covers 8 t-rows.
// ---------------------------------------------------------------------------
__global__ void __launch_bounds__(256)
joint_kernel(const float* __restrict__ Wp,
             const float* __restrict__ bp,
             const int*  __restrict__ targets)
{
    __shared__ float Fs[8][HC_];
    __shared__ float Gs[U1_][HC_ + 4];
    __shared__ float Ws[V_][HC_ + 4];     // Wp transposed: Ws[v][h]
    __shared__ float bps[V_];

    int b  = blockIdx.y;
    int t0 = blockIdx.x * 8;
    int u  = threadIdx.x;                 // 0..63
    int tl = threadIdx.y;                 // 0..3
    int tid = tl * 64 + u;                // 0..255

    if (tid < V_) bps[tid] = bp[tid];

    const float* Fb = g_F + (size_t)(b * T_ + t0) * H_;
    const float* Gb = g_G + (size_t)b * U1_ * H_;

    float acc[2][V_];
    #pragma unroll
    for (int r = 0; r < 2; r++)
        #pragma unroll
        for (int v = 0; v < V_; v++) acc[r][v] = 0.f;

    for (int hc = 0; hc < H_; hc += HC_) {
        // F chunk: 8 rows x 64 = 128 float4 (threads 0..127)
        if (tid < 128) {
            int r = tid >> 4;
            int c = (tid & 15) << 2;
            *(float4*)&Fs[r][c] = *(const float4*)(Fb + (size_t)r * H_ + hc + c);
        }
        // G chunk: 61 x 64 via float4
        for (int i = tid; i < U1_ * (HC_ / 4); i += 256) {
            int r = i / (HC_ / 4);
            int c = (i % (HC_ / 4)) * 4;
            *(float4*)&Gs[r][c] = *(const float4*)(Gb + (size_t)r * H_ + hc + c);
        }
        // Wp^T chunk: 28 x 64 scalars
        for (int i = tid; i < V_ * HC_; i += 256) {
            int v = i >> 6;
            int h = i & 63;
            Ws[v][h] = Wp[(size_t)(hc + h) * V_ + v];
        }
        __syncthreads();

        if (u < U1_) {
            #pragma unroll 2
            for (int h = 0; h < HC_; h += 4) {
                float4 g4 = *(const float4*)&Gs[u][h];
                float4 fa = *(const float4*)&Fs[tl][h];
                float4 fb = *(const float4*)&Fs[tl + 4][h];
                float a0 = fast_tanh(fa.x + g4.x);
                float a1 = fast_tanh(fa.y + g4.y);
                float a2 = fast_tanh(fa.z + g4.z);
                float a3 = fast_tanh(fa.w + g4.w);
                float b0 = fast_tanh(fb.x + g4.x);
                float b1 = fast_tanh(fb.y + g4.y);
                float b2 = fast_tanh(fb.z + g4.z);
                float b3 = fast_tanh(fb.w + g4.w);
                #pragma unroll
                for (int v = 0; v < V_; v++) {
                    float4 w = *(const float4*)&Ws[v][h];
                    float s0 = fmaf(a0, w.x, acc[0][v]);
                    s0 = fmaf(a1, w.y, s0);
                    s0 = fmaf(a2, w.z, s0);
                    acc[0][v] = fmaf(a3, w.w, s0);
                    float s1 = fmaf(b0, w.x, acc[1][v]);
                    s1 = fmaf(b1, w.y, s1);
                    s1 = fmaf(b2, w.z, s1);
                    acc[1][v] = fmaf(b3, w.w, s1);
                }
            }
        }
        __syncthreads();
    }

    if (u < U1_) {
        int tgt = (u < U_) ? targets[b * U_ + u] : 0;
        #pragma unroll
        for (int r = 0; r < 2; r++) {
            int t = t0 + tl + 4 * r;
            float logits[V_];
            float m = -1e30f;
            #pragma unroll
            for (int v = 0; v < V_; v++) {
                logits[v] = acc[r][v] + bps[v];
                m = fmaxf(m, logits[v]);
            }
            float s = 0.f;
            #pragma unroll
            for (int v = 0; v < V_; v++) s += fast_ex2((logits[v] - m) * LOG2E);
            float lse = m + fast_lg2(s) * LN2;

            float lv = logits[0];
            #pragma unroll
            for (int v = 1; v < V_; v++)
                if (v == tgt) lv = logits[v];

            size_t idx = (size_t)(b * T_ + t) * U1_ + u;
            g_blank[idx] = logits[BLANK_] - lse;
            if (u < U_) g_lab[idx] = lv - lse;
        }
    }
}

// ---------------------------------------------------------------------------
// Forward DP, branchless wavefront in log2 domain, approx EX2/LG2 on chain.
// One block per batch. 1024 threads stage lp tables (pre-scaled by log2e)
// into smem; warp 0 runs 459 steps with shfl neighbor exchange.
// ---------------------------------------------------------------------------
__global__ void dp_kernel(const int* __restrict__ t_lens,
                          const int* __restrict__ u_lens,
                          float* __restrict__ out)
{
    extern __shared__ float sm[];
    float* sB = sm;                      // T_*U1_   (log2 domain)
    float* sL = sm + T_ * U1_;           // T_*U1_

    int b   = blockIdx.x;
    int tid = threadIdx.x;               // 1024

    const float4* srcB = (const float4*)(g_blank + (size_t)b * T_ * U1_);
    const float4* srcL = (const float4*)(g_lab   + (size_t)b * T_ * U1_);
    const int n4 = T_ * U1_ / 4;         // 6100
    for (int i = tid; i < n4; i += 1024) {
        float4 vb = srcB[i];
        float4 vl = srcL[i];
        vb.x *= LOG2E; vb.y *= LOG2E; vb.z *= LOG2E; vb.w *= LOG2E;
        vl.x *= LOG2E; vl.y *= LOG2E; vl.z *= LOG2E; vl.w *= LOG2E;
        ((float4*)sB)[i] = vb;
        ((float4*)sL)[i] = vl;
    }
    __syncthreads();
    if (tid >= 32) return;

    const int lane = tid;
    const int Tl = t_lens[b], Ul = u_lens[b];
    const int dcap = (Tl - 1) + Ul;
    const bool cap_lo = (Ul < 32) && (lane == Ul);
    const bool cap_hi = (Ul >= 32) && (lane == Ul - 32);

    const int u_lo = lane;                         // 0..31
    const int u_hi = lane + 32;                    // 32..63
    const int ulo_m1 = max(u_lo - 1, 0);
    const int uhi_c  = min(u_hi, U1_ - 1);
    const int uhi_m1 = min(u_hi - 1, U1_ - 1);

    float a_lo = (lane == 0) ? 0.f : NEGF;
    float a_hi = NEGF;
    float res  = 0.f;

    #pragma unroll 2
    for (int d = 1; d <= (T_ - 1) + (U1_ - 1); d++) {
        float p_lo = __shfl_up_sync(0xffffffffu, a_lo, 1);
        float p_hi = __shfl_up_sync(0xffffffffu, a_hi, 1);
        float lo31 = __shfl_sync(0xffffffffu, a_lo, 31);
        p_lo = (lane == 0) ? NEGF : p_lo;
        p_hi = (lane == 0) ? lo31 : p_hi;

        // lo cell: u = u_lo, t = d - u_lo
        int t  = d - u_lo;
        int i1 = min(max(t - 1, 0), T_ - 1);
        int i2 = min(max(t, 0), T_ - 1);
        float v1 = a_lo + sB[i1 * U1_ + u_lo];
        float v2 = p_lo + sL[i2 * U1_ + ulo_m1];
        float mx = fmaxf(v1, v2), mn = fminf(v1, v2);
        float n_lo = mx + fast_lg2(1.f + fast_ex2(mn - mx));

        // hi cell: u = u_hi, t = d - u_hi
        int th = d - u_hi;
        int j1 = min(max(th - 1, 0), T_ - 1);
        int j2 = min(max(th, 0), T_ - 1);
        float w1 = a_hi + sB[j1 * U1_ + uhi_c];
        float w2 = p_hi + sL[j2 * U1_ + uhi_m1];
        float mxh = fmaxf(w1, w2), mnh = fminf(w1, w2);
        float n_hi = mxh + fast_lg2(1.f + fast_ex2(mnh - mxh));

        bool hit = (d == dcap);
        res = (hit && cap_lo) ? n_lo : res;
        res = (hit && cap_hi) ? n_hi : res;
        a_lo = n_lo;
        a_hi = n_hi;
    }

    if (cap_lo || cap_hi) {
        float blank_fin = g_blank[(size_t)b * T_ * U1_ + (size_t)(Tl - 1) * U1_ + Ul];
        out[b] = -(res * LN2 + blank_fin);
    }
}

// ---------------------------------------------------------------------------
extern "C" void kernel_launch(void* const* d_in, const int* in_sizes, int n_in,
                              void* d_out, int out_size)
{
    const float* enc     = (const float*)d_in[0];
    const float* dec     = (const float*)d_in[1];
    const float* We      = (const float*)d_in[2];
    const float* Wd      = (const float*)d_in[3];
    const float* bf      = (const float*)d_in[4];
    const float* Wp      = (const float*)d_in[5];
    const float* bp      = (const float*)d_in[6];
    const int*   targets = (const int*)d_in[7];
    const int*   t_lens  = (const int*)d_in[8];
    const int*   u_lens  = (const int*)d_in[9];
    float* out = (float*)d_out;

    float *pF = nullptr, *pG = nullptr;
    cudaGetSymbolAddress((void**)&pF, g_F);
    cudaGetSymbolAddress((void**)&pG, g_G);

    static bool attr_set = false;
    const int dp_smem = 2 * T_ * U1_ * sizeof(float);   // 195200 B
    if (!attr_set) {
        cudaFuncSetAttribute(dp_kernel,
                             cudaFuncAttributeMaxDynamicSharedMemorySize, dp_smem);
        attr_set = true;
    }

    gemm_bias_kernel<<<dim3(H_ / 64, (B_ * T_ + 63) / 64), 256>>>(
        enc, We, bf, pF, B_ * T_, H_, E_);
    gemm_bias_kernel<<<dim3(H_ / 64, (B_ * U1_ + 63) / 64), 256>>>(
        dec, Wd, nullptr, pG, B_ * U1_, H_, E_);
    joint_kernel<<<dim3(T_ / 8, B_), dim3(64, 4)>>>(Wp, bp, targets);
    dp_kernel<<<B_, 1024, dp_smem>>>(t_lens, u_lens, out);
}